// round 3
// baseline (speedup 1.0000x reference)
#include <cuda_runtime.h>
#include <cuda_fp16.h>
#include <cstdint>

#define DI __device__ __forceinline__

// problem dims
#define CC   2048
#define WWD  96
#define HWP  4608          // 48*96
#define NCOL 384           // 4*96 GEMM columns

// GEMM tiling
#define BM 64
#define BN 96
#define BK 32
#define KITER (CC/BK)      // 64
#define NST 4
#define AST 40             // padded fp16 row stride (32 + 8) -> conflict-free ldmatrix
#define A_ST (BM*AST)      // 2560 fp16
#define B_ST (BN*AST)      // 3840 fp16
#define STG  (A_ST+B_ST)   // 6400 fp16
#define SMEM_BYTES (NST*STG*2)   // 51200 B

// device scratch (static; allocation-rule safe)
__device__ __half g_w[(size_t)CC * CC];            // 8.4 MB, L2-resident
__device__ __half g_carry[2][(size_t)NCOL * CC];   // 2 x 1.5 MB ping-pong

// ---------------- PTX helpers (base sm_103 ISA only) ----------------
DI uint32_t smem_u32(const void* p) {
    uint32_t a;
    asm("{ .reg .u64 t; cvta.to.shared.u64 t, %1; cvt.u32.u64 %0, t; }" : "=r"(a) : "l"(p));
    return a;
}
DI void cp16(uint32_t s, const void* g) {
    asm volatile("cp.async.cg.shared.global [%0], [%1], 16;" :: "r"(s), "l"(g) : "memory");
}
DI void cp_commit() { asm volatile("cp.async.commit_group;" ::: "memory"); }
DI void cp_wait2()  { asm volatile("cp.async.wait_group 2;" ::: "memory"); }

DI void ldsm4(uint32_t a, uint32_t* r) {
    asm volatile("ldmatrix.sync.aligned.m8n8.x4.shared.b16 {%0,%1,%2,%3},[%4];"
        : "=r"(r[0]), "=r"(r[1]), "=r"(r[2]), "=r"(r[3]) : "r"(a));
}
DI void mma16816(float* d, const uint32_t* a, uint32_t b0, uint32_t b1) {
    asm volatile(
        "mma.sync.aligned.m16n8k16.row.col.f32.f16.f16.f32 "
        "{%0,%1,%2,%3},{%4,%5,%6,%7},{%8,%9},{%0,%1,%2,%3};"
        : "+f"(d[0]), "+f"(d[1]), "+f"(d[2]), "+f"(d[3])
        : "r"(a[0]), "r"(a[1]), "r"(a[2]), "r"(a[3]), "r"(b0), "r"(b1));
}

// ---------------- step GEMM kernel ----------------
// D[o][j] = sum_c W[o][c] * carry[j][c];  y = relu(D + b[o]) + src;  out = y; carry' = fp16(y)
__global__ void __launch_bounds__(128, 1)
step_kernel(int pin, const float* __restrict__ bias,
            const float* __restrict__ src, float* __restrict__ out, int h)
{
    extern __shared__ __half sm[];
    uint32_t smb = smem_u32(sm);
    const __half* __restrict__ cin = g_carry[pin];
    __half* __restrict__ cout = g_carry[pin ^ 1];

    const int tid = threadIdx.x, lane = tid & 31, warp = tid >> 5;
    const int mtile = blockIdx.x, ntile = blockIdx.y;
    const __half* gA = g_w + (size_t)(mtile * BM) * CC;
    const __half* gB = cin + (size_t)(ntile * BN) * CC;

    // ---- cp.async stage loader: 640 16B-units (A:256, B:384), 5 per thread ----
    auto load_stage = [&](int s, int kc) {
        uint32_t base = smb + (uint32_t)(s * STG) * 2;
        #pragma unroll
        for (int i = 0; i < 5; i++) {
            int u = tid + i * 128;
            int isB = (u >= 256);
            int uu = isB ? u - 256 : u;
            int r = uu >> 2, ku = uu & 3;
            uint32_t soff = (isB ? A_ST : 0) + r * AST + ku * 8;
            const __half* g = (isB ? gB : gA) + (size_t)r * CC + kc + ku * 8;
            cp16(base + soff * 2, g);
        }
    };

    #pragma unroll
    for (int s = 0; s < NST - 1; s++) { load_stage(s, s * BK); cp_commit(); }

    const int wm = warp >> 1, wn = warp & 1;
    float acc[2][6][4];
    #pragma unroll
    for (int mi = 0; mi < 2; mi++)
        #pragma unroll
        for (int ni = 0; ni < 6; ni++)
            #pragma unroll
            for (int e = 0; e < 4; e++) acc[mi][ni][e] = 0.f;

    const int lr = lane & 15;
    const int lh = (lane >> 4) * 8;

    #pragma unroll 1
    for (int it = 0; it < KITER; it++) {
        cp_wait2();
        __syncthreads();
        // prefetch stage it+3 (slot was fully consumed at iter it-1; barrier above protects it)
        if (it + NST - 1 < KITER) load_stage((it + NST - 1) & (NST - 1), (it + NST - 1) * BK);
        cp_commit();

        uint32_t base = smb + (uint32_t)((it & (NST - 1)) * STG) * 2;
        #pragma unroll
        for (int kk = 0; kk < BK; kk += 16) {
            uint32_t a[2][4], bt[3][4];
            #pragma unroll
            for (int mi = 0; mi < 2; mi++)
                ldsm4(base + (uint32_t)((wm * 32 + mi * 16 + lr) * AST + kk + lh) * 2, a[mi]);
            // B stored [n][k] == col layout for mma.row.col: NO .trans needed.
            #pragma unroll
            for (int nb = 0; nb < 3; nb++)
                ldsm4(base + (uint32_t)(A_ST + (wn * 48 + nb * 16 + lr) * AST + kk + lh) * 2, bt[nb]);
            #pragma unroll
            for (int mi = 0; mi < 2; mi++)
                #pragma unroll
                for (int nb = 0; nb < 3; nb++) {
                    mma16816(acc[mi][2 * nb],     a[mi], bt[nb][0], bt[nb][2]);
                    mma16816(acc[mi][2 * nb + 1], a[mi], bt[nb][1], bt[nb][3]);
                }
        }
    }

    // ---- epilogue ----
    const int g = lane >> 2, cp2 = (lane & 3) * 2;
    const int o0 = mtile * BM + wm * 32;
    const int n = ntile;
    float bv[2][2];
    #pragma unroll
    for (int mi = 0; mi < 2; mi++) {
        bv[mi][0] = bias[o0 + mi * 16 + g];
        bv[mi][1] = bias[o0 + mi * 16 + g + 8];
    }
    #pragma unroll
    for (int mi = 0; mi < 2; mi++)
        #pragma unroll
        for (int ni = 0; ni < 6; ni++)
            #pragma unroll
            for (int e = 0; e < 4; e++) {
                int o = o0 + mi * 16 + g + (e >> 1) * 8;
                int w = wn * 48 + ni * 8 + cp2 + (e & 1);
                int j = ntile * WWD + w;
                size_t idx = (size_t)(n * CC + o) * HWP + (size_t)h * WWD + w;
                float v = acc[mi][ni][e] + bv[mi][e >> 1];
                v = fmaxf(v, 0.f) + src[idx];
                out[idx] = v;
                cout[(size_t)j * CC + o] = __float2half(v);
            }
}

// ---------------- prep kernels ----------------
__global__ void wprep(const float* __restrict__ W) {
    int i = blockIdx.x * 256 + threadIdx.x;
    if (i >= CC * CC) return;
    g_w[i] = __float2half(W[(size_t)i * 9 + 4]);   // center tap of KH=9
}

__global__ void initk(const float* __restrict__ fea, float* __restrict__ out) {
    int i = blockIdx.x * 256 + threadIdx.x;
    if (i >= NCOL * CC) return;
    int o = i & (CC - 1), j = i >> 11;
    int n = j / WWD, w = j - n * WWD;
    size_t gidx = (size_t)(n * CC + o) * HWP + w;   // h = 0
    float v = fea[gidx];
    out[gidx] = v;                                   // down[0] = x[0]
    g_carry[0][(size_t)j * CC + o] = __float2half(v);
}

// ---------------- launch ----------------
extern "C" void kernel_launch(void* const* d_in, const int* in_sizes, int n_in,
                              void* d_out, int out_size)
{
    const float* fea = (const float*)d_in[0];
    const float* W   = (const float*)d_in[1];
    const float* b   = (const float*)d_in[2];
    float* out = (float*)d_out;

    cudaFuncSetAttribute(step_kernel, cudaFuncAttributeMaxDynamicSharedMemorySize, SMEM_BYTES);

    wprep<<<(CC * CC + 255) / 256, 256>>>(W);
    initk<<<(NCOL * CC + 255) / 256, 256>>>(fea, out);

    int pin = 0;
    for (int i = 0; i < 94; i++) {
        int h = (i < 47) ? (i + 1) : (93 - i);      // forward h=1..47, backward h=46..0
        const float* src = (i < 47) ? fea : out;    // backward residual = down[h] (already in out)
        step_kernel<<<dim3(32, 4), 128, SMEM_BYTES>>>(pin, b, src, out, h);
        pin ^= 1;
    }
}

// round 5
// speedup vs baseline: 1.0592x; 1.0592x over previous
#include <cuda_runtime.h>
#include <cuda_fp16.h>
#include <cstdint>

#define DI __device__ __forceinline__

// problem dims
#define CC   2048
#define WWD  96
#define HWP  4608          // 48*96
#define NCOL 384           // 4*96 GEMM columns

// GEMM tiling
#define BM 64
#define BN 96
#define BK 64
#define KITER (CC/BK)      // 32
#define NST 3
#define AST 72             // padded fp16 row stride (64+8) -> conflict-free ldmatrix
#define A_H (BM*AST)       // 4608 halfs
#define B_H (BN*AST)       // 6912 halfs
#define STG (A_H+B_H)      // 11520 halfs / stage
#define SMEM_BYTES (NST*STG*2)   // 69120 B

// device scratch (static; allocation-rule safe)
__device__ __half g_w[(size_t)CC * CC];            // 8.4 MB, L2-resident
__device__ __half g_carry[2][(size_t)NCOL * CC];   // 2 x 1.5 MB ping-pong

// ---------------- PTX helpers (base sm_103 ISA only) ----------------
DI uint32_t smem_u32(const void* p) {
    uint32_t a;
    asm("{ .reg .u64 t; cvta.to.shared.u64 t, %1; cvt.u32.u64 %0, t; }" : "=r"(a) : "l"(p));
    return a;
}
DI void cp16(uint32_t s, const void* g) {
    asm volatile("cp.async.cg.shared.global [%0], [%1], 16;" :: "r"(s), "l"(g) : "memory");
}
DI void cp_commit() { asm volatile("cp.async.commit_group;" ::: "memory"); }
DI void cp_wait1()  { asm volatile("cp.async.wait_group 1;" ::: "memory"); }

DI void ldsm4(uint32_t a, uint32_t* r) {
    asm volatile("ldmatrix.sync.aligned.m8n8.x4.shared.b16 {%0,%1,%2,%3},[%4];"
        : "=r"(r[0]), "=r"(r[1]), "=r"(r[2]), "=r"(r[3]) : "r"(a));
}
DI void mma16816(float* d, const uint32_t* a, uint32_t b0, uint32_t b1) {
    asm volatile(
        "mma.sync.aligned.m16n8k16.row.col.f32.f16.f16.f32 "
        "{%0,%1,%2,%3},{%4,%5,%6,%7},{%8,%9},{%0,%1,%2,%3};"
        : "+f"(d[0]), "+f"(d[1]), "+f"(d[2]), "+f"(d[3])
        : "r"(a[0]), "r"(a[1]), "r"(a[2]), "r"(a[3]), "r"(b0), "r"(b1));
}

// ---------------- step GEMM kernel ----------------
// D[o][j] = sum_c W[o][c] * carry[j][c];  y = relu(D + b[o]) + src;  out = y; carry' = fp16(y)
__global__ void __launch_bounds__(256, 1)
step_kernel(int pin, const float* __restrict__ bias,
            const float* __restrict__ src, float* __restrict__ out, int h)
{
    extern __shared__ __half sm[];
    uint32_t smb = smem_u32(sm);
    const __half* __restrict__ cin = g_carry[pin];
    __half* __restrict__ cout = g_carry[pin ^ 1];

    const int tid = threadIdx.x, lane = tid & 31, warp = tid >> 5;
    const int mtile = blockIdx.x, ntile = blockIdx.y;
    const __half* gA = g_w + (size_t)(mtile * BM) * CC;
    const __half* gB = cin + (size_t)(ntile * BN) * CC;

    // ---- cp.async stage loader: 1280 16B-units (A:512, B:768), 5 per thread ----
    auto load_stage = [&](int s, int kc) {
        uint32_t base = smb + (uint32_t)(s * STG) * 2;
        #pragma unroll
        for (int i = 0; i < 5; i++) {
            int u = tid + i * 256;
            int isB = (u >= 512);
            int uu = isB ? u - 512 : u;
            int r = uu >> 3, ku = uu & 7;
            uint32_t soff = (isB ? A_H : 0) + r * AST + ku * 8;
            const __half* g = (isB ? gB : gA) + (size_t)r * CC + kc + ku * 8;
            cp16(base + soff * 2, g);
        }
    };

    #pragma unroll
    for (int s = 0; s < NST - 1; s++) { load_stage(s, s * BK); cp_commit(); }

    // 8 warps: wm 0..3 (16 rows each), wn 0..1 (48 cols each)
    const int wm = warp >> 1, wn = warp & 1;
    float acc[6][4];
    #pragma unroll
    for (int ni = 0; ni < 6; ni++)
        #pragma unroll
        for (int e = 0; e < 4; e++) acc[ni][e] = 0.f;

    const int lr = lane & 15;
    const int lh = (lane >> 4) * 8;
    const uint32_t aoff = (uint32_t)((wm * 16 + lr) * AST + lh) * 2;
    const uint32_t boff0 = (uint32_t)(A_H + (wn * 48 + lr) * AST + lh) * 2;

    #pragma unroll 1
    for (int it = 0; it < KITER; it++) {
        cp_wait1();
        __syncthreads();
        if (it + NST - 1 < KITER) load_stage((it + NST - 1) % NST, (it + NST - 1) * BK);
        cp_commit();

        uint32_t base = smb + (uint32_t)((it % NST) * STG) * 2;
        uint32_t a[2][4], b[2][3][4];
        // preload kk=0 fragments
        ldsm4(base + aoff, a[0]);
        #pragma unroll
        for (int nb = 0; nb < 3; nb++)
            ldsm4(base + boff0 + (uint32_t)(nb * 16 * AST) * 2, b[0][nb]);

        #pragma unroll
        for (int kk = 0; kk < BK / 16; kk++) {
            int cur = kk & 1, nxt = cur ^ 1;
            if (kk + 1 < BK / 16) {
                uint32_t ko = (uint32_t)((kk + 1) * 16) * 2;
                ldsm4(base + aoff + ko, a[nxt]);
                #pragma unroll
                for (int nb = 0; nb < 3; nb++)
                    ldsm4(base + boff0 + (uint32_t)(nb * 16 * AST) * 2 + ko, b[nxt][nb]);
            }
            #pragma unroll
            for (int nb = 0; nb < 3; nb++) {
                mma16816(acc[2 * nb],     a[cur], b[cur][nb][0], b[cur][nb][2]);
                mma16816(acc[2 * nb + 1], a[cur], b[cur][nb][1], b[cur][nb][3]);
            }
        }
    }

    // ---- epilogue ----
    const int g = lane >> 2, cp2 = (lane & 3) * 2;
    const int o0 = mtile * BM + wm * 16;
    const int n = ntile;
    float bv0 = bias[o0 + g], bv1 = bias[o0 + g + 8];
    #pragma unroll
    for (int ni = 0; ni < 6; ni++)
        #pragma unroll
        for (int e = 0; e < 4; e++) {
            int o = o0 + g + (e >> 1) * 8;
            int w = wn * 48 + ni * 8 + cp2 + (e & 1);
            int j = ntile * WWD + w;
            size_t idx = (size_t)(n * CC + o) * HWP + (size_t)h * WWD + w;
            float v = acc[ni][e] + ((e >> 1) ? bv1 : bv0);
            v = fmaxf(v, 0.f) + src[idx];
            out[idx] = v;
            cout[(size_t)j * CC + o] = __float2half(v);
        }
}

// ---------------- prep kernels ----------------
__global__ void wprep(const float* __restrict__ W) {
    int i = blockIdx.x * 256 + threadIdx.x;
    if (i >= CC * CC) return;
    g_w[i] = __float2half(W[(size_t)i * 9 + 4]);   // center tap of KH=9
}

__global__ void initk(const float* __restrict__ fea, float* __restrict__ out) {
    int i = blockIdx.x * 256 + threadIdx.x;
    if (i >= NCOL * CC) return;
    int o = i & (CC - 1), j = i >> 11;
    int n = j / WWD, w = j - n * WWD;
    size_t gidx = (size_t)(n * CC + o) * HWP + w;   // h = 0
    float v = fea[gidx];
    out[gidx] = v;                                   // down[0] = x[0]
    g_carry[0][(size_t)j * CC + o] = __float2half(v);
}

// ---------------- launch ----------------
extern "C" void kernel_launch(void* const* d_in, const int* in_sizes, int n_in,
                              void* d_out, int out_size)
{
    const float* fea = (const float*)d_in[0];
    const float* W   = (const float*)d_in[1];
    const float* b   = (const float*)d_in[2];
    float* out = (float*)d_out;

    cudaFuncSetAttribute(step_kernel, cudaFuncAttributeMaxDynamicSharedMemorySize, SMEM_BYTES);

    wprep<<<(CC * CC + 255) / 256, 256>>>(W);
    initk<<<(NCOL * CC + 255) / 256, 256>>>(fea, out);

    int pin = 0;
    for (int i = 0; i < 94; i++) {
        int h = (i < 47) ? (i + 1) : (93 - i);      // forward h=1..47, backward h=46..0
        const float* src = (i < 47) ? fea : out;    // backward residual = down[h] (already in out)
        step_kernel<<<dim3(32, 4), 256, SMEM_BYTES>>>(pin, b, src, out, h);
        pin ^= 1;
    }
}